// round 3
// baseline (speedup 1.0000x reference)
#include <cuda_runtime.h>
#include <math.h>
#include <float.h>
#include <stdint.h>

#define B_    4
#define NIN_  4096
#define M_    16384
#define CIN_  256
#define COUT_ 128

typedef unsigned long long ull;

// ---------------- f32x2 packed helpers (sm_103a FFMA2 path) ----------------
__device__ __forceinline__ ull pack2(float lo, float hi) {
    ull r; asm("mov.b64 %0,{%1,%2};" : "=l"(r) : "f"(lo), "f"(hi)); return r;
}
__device__ __forceinline__ void unpack2(float& lo, float& hi, ull v) {
    asm("mov.b64 {%0,%1},%2;" : "=f"(lo), "=f"(hi) : "l"(v));
}
__device__ __forceinline__ ull fma2(ull a, ull b, ull c) {
    ull d; asm("fma.rn.f32x2 %0,%1,%2,%3;" : "=l"(d) : "l"(a), "l"(b), "l"(c)); return d;
}
__device__ __forceinline__ ull mul2(ull a, ull b) {
    ull d; asm("mul.rn.f32x2 %0,%1,%2;" : "=l"(d) : "l"(a), "l"(b)); return d;
}
__device__ __forceinline__ ull add2(ull a, ull b) {
    ull d; asm("add.rn.f32x2 %0,%1,%2;" : "=l"(d) : "l"(a), "l"(b)); return d;
}

// ---------------- scratch ----------------
__device__ float g_bufA[B_ * COUT_ * NIN_];
__device__ float g_bufB[B_ * COUT_ * NIN_];
__device__ float g_featT[B_ * NIN_ * COUT_];
__device__ float g_wv[B_ * M_ * 3];
__device__ int   g_iv[B_ * M_ * 3];

// ---------------- fused Conv1d(k=1) + BN + ReLU GEMM (f32x2 inner loop) ----------------
__global__ __launch_bounds__(256) void mlp_kernel(
    const float* __restrict__ X, const float* __restrict__ W,
    const float* __restrict__ bias, const float* __restrict__ gamma,
    const float* __restrict__ betap, const float* __restrict__ rmean,
    const float* __restrict__ rvar, float* __restrict__ Y,
    int K, int transposed)
{
    __shared__ float Ws[32][COUT_];
    __shared__ float Xs[32][64];
    const int tid = threadIdx.x;
    const int b   = blockIdx.y;
    const int n0  = blockIdx.x * 64;
    const float* Xb = X + (size_t)b * K * NIN_;

    // acc2[p][j]: lanes = (cout0+2p, cout0+2p+1) at column nl+j
    ull acc2[4][4];
#pragma unroll
    for (int p = 0; p < 4; p++)
#pragma unroll
        for (int j = 0; j < 4; j++) acc2[p][j] = 0ull;   // (0.f, 0.f)

    const int rg    = tid >> 4;
    const int cg    = tid & 15;
    const int cout0 = rg * 8;
    const int nl    = cg * 4;

    for (int k0 = 0; k0 < K; k0 += 32) {
#pragma unroll
        for (int l = 0; l < 4; l++) {
            int idx = tid + l * 256;
            int co  = idx & 127;
            int kq  = idx >> 7;
            float4 w4 = *(const float4*)(W + (size_t)co * K + k0 + kq * 4);
            Ws[kq * 4 + 0][co] = w4.x;
            Ws[kq * 4 + 1][co] = w4.y;
            Ws[kq * 4 + 2][co] = w4.z;
            Ws[kq * 4 + 3][co] = w4.w;
        }
#pragma unroll
        for (int l = 0; l < 2; l++) {
            int idx = tid + l * 256;
            int nq  = idx & 15;
            int kk  = idx >> 4;
            *(float4*)&Xs[kk][nq * 4] =
                *(const float4*)(Xb + (size_t)(k0 + kk) * NIN_ + n0 + nq * 4);
        }
        __syncthreads();
#pragma unroll
        for (int k = 0; k < 32; k++) {
            ull ap[4];
#pragma unroll
            for (int p = 0; p < 4; p++)
                ap[p] = *(const ull*)&Ws[k][cout0 + 2 * p];
            float4 xb = *(const float4*)&Xs[k][nl];
            ull xd[4];
            xd[0] = pack2(xb.x, xb.x);
            xd[1] = pack2(xb.y, xb.y);
            xd[2] = pack2(xb.z, xb.z);
            xd[3] = pack2(xb.w, xb.w);
#pragma unroll
            for (int p = 0; p < 4; p++)
#pragma unroll
                for (int j = 0; j < 4; j++)
                    acc2[p][j] = fma2(ap[p], xd[j], acc2[p][j]);
        }
        __syncthreads();
    }

    // unpack (bitwise same accumulation order as scalar version)
    float acc[8][4];
#pragma unroll
    for (int p = 0; p < 4; p++)
#pragma unroll
        for (int j = 0; j < 4; j++)
            unpack2(acc[2 * p][j], acc[2 * p + 1][j], acc2[p][j]);

    float sc[8], shf[8];
#pragma unroll
    for (int i = 0; i < 8; i++) {
        int c = cout0 + i;
        float s = gamma[c] / sqrtf(rvar[c] + 1e-5f);
        sc[i]  = s;
        shf[i] = betap[c] + (bias[c] - rmean[c]) * s;
    }

    if (!transposed) {
#pragma unroll
        for (int i = 0; i < 8; i++) {
            float4 v;
            v.x = fmaxf(__fmaf_rn(acc[i][0], sc[i], shf[i]), 0.f);
            v.y = fmaxf(__fmaf_rn(acc[i][1], sc[i], shf[i]), 0.f);
            v.z = fmaxf(__fmaf_rn(acc[i][2], sc[i], shf[i]), 0.f);
            v.w = fmaxf(__fmaf_rn(acc[i][3], sc[i], shf[i]), 0.f);
            *(float4*)(Y + ((size_t)b * COUT_ + cout0 + i) * NIN_ + n0 + nl) = v;
        }
    } else {
#pragma unroll
        for (int j = 0; j < 4; j++) {
            float v[8];
#pragma unroll
            for (int i = 0; i < 8; i++)
                v[i] = fmaxf(__fmaf_rn(acc[i][j], sc[i], shf[i]), 0.f);
            float* p = Y + ((size_t)b * NIN_ + n0 + nl + j) * COUT_ + cout0;
            *(float4*)(p)     = make_float4(v[0], v[1], v[2], v[3]);
            *(float4*)(p + 4) = make_float4(v[4], v[5], v[6], v[7]);
        }
    }
}

// ---------------- brute-force exact top-3 scan, f32x2 packed over candidate pairs ----------------
// Arithmetic is bitwise identical to the reference algebra:
//   sum = (x*x + y*y) + z*z ; dot = fma(z,z',fma(y,y',x*x')) ; d = fma(-2,dot,sum_o+sum_i)
// Clamp (<0 -> 1e-7) is hoisted out of the common path: since s2 > 1e-7,
// clamp(d) < s2  <=>  implied by  min(dlo,dhi) < s2 (over-approx); exact clamped
// compares are redone inside the rare branch, so selection is bitwise identical.
#define INSERT3(d_, j_, s0_, s1_, s2_, i0_, i1_, i2_)                      \
    if (d_ < s2_) {                                                        \
        if (d_ < s1_) {                                                    \
            s2_ = s1_; i2_ = i1_;                                          \
            if (d_ < s0_) { s1_ = s0_; i1_ = i0_; s0_ = d_; i0_ = j_; }    \
            else          { s1_ = d_;  i1_ = j_; }                         \
        } else { s2_ = d_; i2_ = j_; }                                     \
    }

__global__ __launch_bounds__(256) void scan_kernel(
    const float* __restrict__ xyzin, const float* __restrict__ xyzout,
    float* __restrict__ wout, int* __restrict__ iout)
{
    extern __shared__ float sm[];
    float* xs = sm;
    float* ys = sm + NIN_;
    float* zs = sm + 2 * NIN_;
    float* ss = sm + 3 * NIN_;
    const int tid = threadIdx.x;
    const int b   = blockIdx.y;
    const float* pin = xyzin + (size_t)b * NIN_ * 3;

    for (int j = tid; j < NIN_; j += 256) {
        float x = pin[j * 3 + 0];
        float y = pin[j * 3 + 1];
        float z = pin[j * 3 + 2];
        xs[j] = x; ys[j] = y; zs[j] = z;
        ss[j] = __fadd_rn(__fadd_rn(__fmul_rn(x, x), __fmul_rn(y, y)),
                          __fmul_rn(z, z));
    }
    __syncthreads();

    // two queries per thread: m0 and m0+256
    const int m0 = blockIdx.x * 512 + tid;
    const int m1 = m0 + 256;

    const float* q0 = xyzout + ((size_t)b * M_ + m0) * 3;
    const float* q1 = xyzout + ((size_t)b * M_ + m1) * 3;
    float q0x = q0[0], q0y = q0[1], q0z = q0[2];
    float q1x = q1[0], q1y = q1[1], q1z = q1[2];
    float q0n = __fadd_rn(__fadd_rn(__fmul_rn(q0x, q0x), __fmul_rn(q0y, q0y)),
                          __fmul_rn(q0z, q0z));
    float q1n = __fadd_rn(__fadd_rn(__fmul_rn(q1x, q1x), __fmul_rn(q1y, q1y)),
                          __fmul_rn(q1z, q1z));

    const ull qx20 = pack2(q0x, q0x), qy20 = pack2(q0y, q0y);
    const ull qz20 = pack2(q0z, q0z), qn20 = pack2(q0n, q0n);
    const ull qx21 = pack2(q1x, q1x), qy21 = pack2(q1y, q1y);
    const ull qz21 = pack2(q1z, q1z), qn21 = pack2(q1n, q1n);
    const ull n22  = pack2(-2.0f, -2.0f);

    float a_s0 = FLT_MAX, a_s1 = FLT_MAX, a_s2 = FLT_MAX;
    float b_s0 = FLT_MAX, b_s1 = FLT_MAX, b_s2 = FLT_MAX;
    int a_i0 = 0, a_i1 = 0, a_i2 = 0;
    int b_i0 = 0, b_i1 = 0, b_i2 = 0;

    const ull* xs2 = (const ull*)xs;
    const ull* ys2 = (const ull*)ys;
    const ull* zs2 = (const ull*)zs;
    const ull* ss2 = (const ull*)ss;

#pragma unroll 4
    for (int jp = 0; jp < NIN_ / 2; jp++) {
        ull xp = xs2[jp], yp = ys2[jp], zp = zs2[jp], sp = ss2[jp];

        // query 0
        {
            ull dot = fma2(qz20, zp, fma2(qy20, yp, mul2(qx20, xp)));
            ull d2  = fma2(n22, dot, add2(qn20, sp));
            float dlo, dhi; unpack2(dlo, dhi, d2);
            if (__builtin_expect(fminf(dlo, dhi) < a_s2, 0)) {
                float cl = (dlo < 0.0f) ? 1e-7f : dlo;
                float ch = (dhi < 0.0f) ? 1e-7f : dhi;
                int j = 2 * jp;
                INSERT3(cl, j,     a_s0, a_s1, a_s2, a_i0, a_i1, a_i2);
                INSERT3(ch, j + 1, a_s0, a_s1, a_s2, a_i0, a_i1, a_i2);
            }
        }
        // query 1
        {
            ull dot = fma2(qz21, zp, fma2(qy21, yp, mul2(qx21, xp)));
            ull d2  = fma2(n22, dot, add2(qn21, sp));
            float dlo, dhi; unpack2(dlo, dhi, d2);
            if (__builtin_expect(fminf(dlo, dhi) < b_s2, 0)) {
                float cl = (dlo < 0.0f) ? 1e-7f : dlo;
                float ch = (dhi < 0.0f) ? 1e-7f : dhi;
                int j = 2 * jp;
                INSERT3(cl, j,     b_s0, b_s1, b_s2, b_i0, b_i1, b_i2);
                INSERT3(ch, j + 1, b_s0, b_s1, b_s2, b_i0, b_i1, b_i2);
            }
        }
    }

    {
        float w0 = __fdiv_rn(1.0f, a_s0);
        float w1 = __fdiv_rn(1.0f, a_s1);
        float w2 = __fdiv_rn(1.0f, a_s2);
        float wsum = __fadd_rn(__fadd_rn(w0, w1), w2);
        size_t o = ((size_t)b * M_ + m0) * 3;
        wout[o + 0] = __fdiv_rn(w0, wsum);
        wout[o + 1] = __fdiv_rn(w1, wsum);
        wout[o + 2] = __fdiv_rn(w2, wsum);
        iout[o + 0] = a_i0; iout[o + 1] = a_i1; iout[o + 2] = a_i2;
    }
    {
        float w0 = __fdiv_rn(1.0f, b_s0);
        float w1 = __fdiv_rn(1.0f, b_s1);
        float w2 = __fdiv_rn(1.0f, b_s2);
        float wsum = __fadd_rn(__fadd_rn(w0, w1), w2);
        size_t o = ((size_t)b * M_ + m1) * 3;
        wout[o + 0] = __fdiv_rn(w0, wsum);
        wout[o + 1] = __fdiv_rn(w1, wsum);
        wout[o + 2] = __fdiv_rn(w2, wsum);
        iout[o + 0] = b_i0; iout[o + 1] = b_i1; iout[o + 2] = b_i2;
    }
}

// ---------------- gather + weighted interpolation ----------------
__global__ __launch_bounds__(128) void interp_kernel(
    const float* __restrict__ featT, const float* __restrict__ wv,
    const int* __restrict__ iv, float* __restrict__ out)
{
    __shared__ float sacc[64][COUT_ + 1];
    __shared__ float sw[64 * 3];
    __shared__ int   si[64 * 3];
    const int tid = threadIdx.x;
    const int b   = blockIdx.y;
    const int m0  = blockIdx.x * 64;
    const size_t base = ((size_t)b * M_ + m0) * 3;

    for (int l = tid; l < 192; l += 128) {
        sw[l] = wv[base + l];
        si[l] = iv[base + l];
    }
    __syncthreads();

    const float* fb = featT + (size_t)b * NIN_ * COUT_;
    const int c = tid;
#pragma unroll 2
    for (int qq = 0; qq < 64; qq++) {
        float w0 = sw[qq * 3], w1 = sw[qq * 3 + 1], w2 = sw[qq * 3 + 2];
        const float* f0 = fb + (size_t)si[qq * 3]     * COUT_;
        const float* f1 = fb + (size_t)si[qq * 3 + 1] * COUT_;
        const float* f2 = fb + (size_t)si[qq * 3 + 2] * COUT_;
        sacc[qq][c] = __fmaf_rn(w2, f2[c],
                      __fmaf_rn(w1, f1[c], __fmul_rn(w0, f0[c])));
    }
    __syncthreads();

#pragma unroll
    for (int cc = 0; cc < COUT_; cc += 2) {
        int ci = cc + (tid >> 6);
        int mi = tid & 63;
        out[((size_t)b * COUT_ + ci) * M_ + m0 + mi] = sacc[mi][ci];
    }
}

// ---------------- launch ----------------
extern "C" void kernel_launch(void* const* d_in, const int* in_sizes, int n_in,
                              void* d_out, int out_size)
{
    (void)in_sizes; (void)n_in; (void)out_size;
    const float* rgb    = (const float*)d_in[0];
    const float* xyzin  = (const float*)d_in[1];
    const float* xyzout = (const float*)d_in[2];
    const float* w1 = (const float*)d_in[3];
    const float* b1 = (const float*)d_in[4];
    const float* g1 = (const float*)d_in[5];
    const float* be1 = (const float*)d_in[6];
    const float* rm1 = (const float*)d_in[7];
    const float* rv1 = (const float*)d_in[8];
    const float* w2 = (const float*)d_in[9];
    const float* b2 = (const float*)d_in[10];
    const float* g2 = (const float*)d_in[11];
    const float* be2 = (const float*)d_in[12];
    const float* rm2 = (const float*)d_in[13];
    const float* rv2 = (const float*)d_in[14];
    const float* w3 = (const float*)d_in[15];
    const float* b3 = (const float*)d_in[16];
    const float* g3 = (const float*)d_in[17];
    const float* be3 = (const float*)d_in[18];
    const float* rm3 = (const float*)d_in[19];
    const float* rv3 = (const float*)d_in[20];
    float* out = (float*)d_out;

    float *bufA, *bufB, *featT, *wvp;
    int* ivp;
    cudaGetSymbolAddress((void**)&bufA,  g_bufA);
    cudaGetSymbolAddress((void**)&bufB,  g_bufB);
    cudaGetSymbolAddress((void**)&featT, g_featT);
    cudaGetSymbolAddress((void**)&wvp,   g_wv);
    cudaGetSymbolAddress((void**)&ivp,   g_iv);

    dim3 gemm_grid(NIN_ / 64, B_);
    mlp_kernel<<<gemm_grid, 256>>>(rgb,  w1, b1, g1, be1, rm1, rv1, bufA,  CIN_,  0);
    mlp_kernel<<<gemm_grid, 256>>>(bufA, w2, b2, g2, be2, rm2, rv2, bufB,  COUT_, 0);
    mlp_kernel<<<gemm_grid, 256>>>(bufB, w3, b3, g3, be3, rm3, rv3, featT, COUT_, 1);

    cudaFuncSetAttribute(scan_kernel,
                         cudaFuncAttributeMaxDynamicSharedMemorySize,
                         4 * NIN_ * (int)sizeof(float));
    dim3 scan_grid(M_ / 512, B_);
    scan_kernel<<<scan_grid, 256, 4 * NIN_ * sizeof(float)>>>(xyzin, xyzout, wvp, ivp);

    dim3 interp_grid(M_ / 64, B_);
    interp_kernel<<<interp_grid, 128>>>(featT, wvp, ivp, out);
}

// round 4
// speedup vs baseline: 1.3485x; 1.3485x over previous
#include <cuda_runtime.h>
#include <math.h>
#include <float.h>
#include <stdint.h>

#define B_    4
#define NIN_  4096
#define M_    16384
#define CIN_  256
#define COUT_ 128
#define NSEG_ 4
#define SEGC_ (NIN_ / NSEG_)   // 1024 candidates per segment

typedef unsigned long long ull;

// ---------------- f32x2 packed helpers (sm_103a FFMA2 path) ----------------
__device__ __forceinline__ ull pack2(float lo, float hi) {
    ull r; asm("mov.b64 %0,{%1,%2};" : "=l"(r) : "f"(lo), "f"(hi)); return r;
}
__device__ __forceinline__ void unpack2(float& lo, float& hi, ull v) {
    asm("mov.b64 {%0,%1},%2;" : "=f"(lo), "=f"(hi) : "l"(v));
}
__device__ __forceinline__ ull fma2(ull a, ull b, ull c) {
    ull d; asm("fma.rn.f32x2 %0,%1,%2,%3;" : "=l"(d) : "l"(a), "l"(b), "l"(c)); return d;
}
__device__ __forceinline__ ull mul2(ull a, ull b) {
    ull d; asm("mul.rn.f32x2 %0,%1,%2;" : "=l"(d) : "l"(a), "l"(b)); return d;
}
__device__ __forceinline__ ull add2(ull a, ull b) {
    ull d; asm("add.rn.f32x2 %0,%1,%2;" : "=l"(d) : "l"(a), "l"(b)); return d;
}

// ---------------- scratch ----------------
__device__ float g_bufA[B_ * COUT_ * NIN_];
__device__ float g_bufB[B_ * COUT_ * NIN_];
__device__ float g_featT[B_ * NIN_ * COUT_];
__device__ float g_wv[B_ * M_ * 3];
__device__ int   g_iv[B_ * M_ * 3];
__device__ float g_pval[B_ * NSEG_ * M_ * 3];   // partial top-3 values
__device__ int   g_pidx[B_ * NSEG_ * M_ * 3];   // partial top-3 indices

// ---------------- fused Conv1d(k=1) + BN + ReLU GEMM (f32x2 inner loop) ----------------
__global__ __launch_bounds__(256) void mlp_kernel(
    const float* __restrict__ X, const float* __restrict__ W,
    const float* __restrict__ bias, const float* __restrict__ gamma,
    const float* __restrict__ betap, const float* __restrict__ rmean,
    const float* __restrict__ rvar, float* __restrict__ Y,
    int K, int transposed)
{
    __shared__ float Ws[32][COUT_];
    __shared__ float Xs[32][64];
    const int tid = threadIdx.x;
    const int b   = blockIdx.y;
    const int n0  = blockIdx.x * 64;
    const float* Xb = X + (size_t)b * K * NIN_;

    ull acc2[4][4];
#pragma unroll
    for (int p = 0; p < 4; p++)
#pragma unroll
        for (int j = 0; j < 4; j++) acc2[p][j] = 0ull;

    const int rg    = tid >> 4;
    const int cg    = tid & 15;
    const int cout0 = rg * 8;
    const int nl    = cg * 4;

    for (int k0 = 0; k0 < K; k0 += 32) {
#pragma unroll
        for (int l = 0; l < 4; l++) {
            int idx = tid + l * 256;
            int co  = idx & 127;
            int kq  = idx >> 7;
            float4 w4 = *(const float4*)(W + (size_t)co * K + k0 + kq * 4);
            Ws[kq * 4 + 0][co] = w4.x;
            Ws[kq * 4 + 1][co] = w4.y;
            Ws[kq * 4 + 2][co] = w4.z;
            Ws[kq * 4 + 3][co] = w4.w;
        }
#pragma unroll
        for (int l = 0; l < 2; l++) {
            int idx = tid + l * 256;
            int nq  = idx & 15;
            int kk  = idx >> 4;
            *(float4*)&Xs[kk][nq * 4] =
                *(const float4*)(Xb + (size_t)(k0 + kk) * NIN_ + n0 + nq * 4);
        }
        __syncthreads();
#pragma unroll
        for (int k = 0; k < 32; k++) {
            ull ap[4];
#pragma unroll
            for (int p = 0; p < 4; p++)
                ap[p] = *(const ull*)&Ws[k][cout0 + 2 * p];
            float4 xb = *(const float4*)&Xs[k][nl];
            ull xd[4];
            xd[0] = pack2(xb.x, xb.x);
            xd[1] = pack2(xb.y, xb.y);
            xd[2] = pack2(xb.z, xb.z);
            xd[3] = pack2(xb.w, xb.w);
#pragma unroll
            for (int p = 0; p < 4; p++)
#pragma unroll
                for (int j = 0; j < 4; j++)
                    acc2[p][j] = fma2(ap[p], xd[j], acc2[p][j]);
        }
        __syncthreads();
    }

    float acc[8][4];
#pragma unroll
    for (int p = 0; p < 4; p++)
#pragma unroll
        for (int j = 0; j < 4; j++)
            unpack2(acc[2 * p][j], acc[2 * p + 1][j], acc2[p][j]);

    float sc[8], shf[8];
#pragma unroll
    for (int i = 0; i < 8; i++) {
        int c = cout0 + i;
        float s = gamma[c] / sqrtf(rvar[c] + 1e-5f);
        sc[i]  = s;
        shf[i] = betap[c] + (bias[c] - rmean[c]) * s;
    }

    if (!transposed) {
#pragma unroll
        for (int i = 0; i < 8; i++) {
            float4 v;
            v.x = fmaxf(__fmaf_rn(acc[i][0], sc[i], shf[i]), 0.f);
            v.y = fmaxf(__fmaf_rn(acc[i][1], sc[i], shf[i]), 0.f);
            v.z = fmaxf(__fmaf_rn(acc[i][2], sc[i], shf[i]), 0.f);
            v.w = fmaxf(__fmaf_rn(acc[i][3], sc[i], shf[i]), 0.f);
            *(float4*)(Y + ((size_t)b * COUT_ + cout0 + i) * NIN_ + n0 + nl) = v;
        }
    } else {
#pragma unroll
        for (int j = 0; j < 4; j++) {
            float v[8];
#pragma unroll
            for (int i = 0; i < 8; i++)
                v[i] = fmaxf(__fmaf_rn(acc[i][j], sc[i], shf[i]), 0.f);
            float* p = Y + ((size_t)b * NIN_ + n0 + nl + j) * COUT_ + cout0;
            *(float4*)(p)     = make_float4(v[0], v[1], v[2], v[3]);
            *(float4*)(p + 4) = make_float4(v[4], v[5], v[6], v[7]);
        }
    }
}

// ---------------- segmented exact top-3 scan ----------------
// Each block scans SEGC_=1024 candidates for 512 queries (Q=2/thread).
// Per-candidate arithmetic bitwise identical to reference algebra; clamp hoisted
// out of common path (s2 > 1e-7 always, exact clamped compare redone in branch).
// Partial triples are strict-<-inserted in ascending index order -> merging
// with (val, idx) lexicographic order reproduces stable top_k exactly.
#define INSERT3(d_, j_, s0_, s1_, s2_, i0_, i1_, i2_)                      \
    if (d_ < s2_) {                                                        \
        if (d_ < s1_) {                                                    \
            s2_ = s1_; i2_ = i1_;                                          \
            if (d_ < s0_) { s1_ = s0_; i1_ = i0_; s0_ = d_; i0_ = j_; }    \
            else          { s1_ = d_;  i1_ = j_; }                         \
        } else { s2_ = d_; i2_ = j_; }                                     \
    }

__global__ __launch_bounds__(256) void scan_kernel(
    const float* __restrict__ xyzin, const float* __restrict__ xyzout,
    float* __restrict__ pval, int* __restrict__ pidx)
{
    __shared__ __align__(16) float xs[SEGC_];
    __shared__ __align__(16) float ys[SEGC_];
    __shared__ __align__(16) float zs[SEGC_];
    __shared__ __align__(16) float ss[SEGC_];

    const int tid = threadIdx.x;
    const int seg = blockIdx.y;
    const int b   = blockIdx.z;
    const int jbase = seg * SEGC_;
    const float* pin = xyzin + ((size_t)b * NIN_ + jbase) * 3;

    for (int j = tid; j < SEGC_; j += 256) {
        float x = pin[j * 3 + 0];
        float y = pin[j * 3 + 1];
        float z = pin[j * 3 + 2];
        xs[j] = x; ys[j] = y; zs[j] = z;
        ss[j] = __fadd_rn(__fadd_rn(__fmul_rn(x, x), __fmul_rn(y, y)),
                          __fmul_rn(z, z));
    }
    __syncthreads();

    const int m0 = blockIdx.x * 512 + tid;
    const int m1 = m0 + 256;

    const float* q0 = xyzout + ((size_t)b * M_ + m0) * 3;
    const float* q1 = xyzout + ((size_t)b * M_ + m1) * 3;
    float q0x = q0[0], q0y = q0[1], q0z = q0[2];
    float q1x = q1[0], q1y = q1[1], q1z = q1[2];
    float q0n = __fadd_rn(__fadd_rn(__fmul_rn(q0x, q0x), __fmul_rn(q0y, q0y)),
                          __fmul_rn(q0z, q0z));
    float q1n = __fadd_rn(__fadd_rn(__fmul_rn(q1x, q1x), __fmul_rn(q1y, q1y)),
                          __fmul_rn(q1z, q1z));

    const ull qx20 = pack2(q0x, q0x), qy20 = pack2(q0y, q0y);
    const ull qz20 = pack2(q0z, q0z), qn20 = pack2(q0n, q0n);
    const ull qx21 = pack2(q1x, q1x), qy21 = pack2(q1y, q1y);
    const ull qz21 = pack2(q1z, q1z), qn21 = pack2(q1n, q1n);
    const ull n22  = pack2(-2.0f, -2.0f);

    float a_s0 = FLT_MAX, a_s1 = FLT_MAX, a_s2 = FLT_MAX;
    float b_s0 = FLT_MAX, b_s1 = FLT_MAX, b_s2 = FLT_MAX;
    int a_i0 = 0, a_i1 = 0, a_i2 = 0;
    int b_i0 = 0, b_i1 = 0, b_i2 = 0;

    const ulonglong2* xs4 = (const ulonglong2*)xs;
    const ulonglong2* ys4 = (const ulonglong2*)ys;
    const ulonglong2* zs4 = (const ulonglong2*)zs;
    const ulonglong2* ss4 = (const ulonglong2*)ss;

#pragma unroll 2
    for (int jq = 0; jq < SEGC_ / 4; jq++) {
        ulonglong2 xq = xs4[jq], yq = ys4[jq], zq = zs4[jq], sq = ss4[jq];
#pragma unroll
        for (int p = 0; p < 2; p++) {
            ull xp = p ? xq.y : xq.x;
            ull yp = p ? yq.y : yq.x;
            ull zp = p ? zq.y : zq.x;
            ull sp = p ? sq.y : sq.x;
            int j = jbase + 4 * jq + 2 * p;
            // query 0
            {
                ull dot = fma2(qz20, zp, fma2(qy20, yp, mul2(qx20, xp)));
                ull d2  = fma2(n22, dot, add2(qn20, sp));
                float dlo, dhi; unpack2(dlo, dhi, d2);
                if (__builtin_expect(fminf(dlo, dhi) < a_s2, 0)) {
                    float cl = (dlo < 0.0f) ? 1e-7f : dlo;
                    float ch = (dhi < 0.0f) ? 1e-7f : dhi;
                    INSERT3(cl, j,     a_s0, a_s1, a_s2, a_i0, a_i1, a_i2);
                    INSERT3(ch, j + 1, a_s0, a_s1, a_s2, a_i0, a_i1, a_i2);
                }
            }
            // query 1
            {
                ull dot = fma2(qz21, zp, fma2(qy21, yp, mul2(qx21, xp)));
                ull d2  = fma2(n22, dot, add2(qn21, sp));
                float dlo, dhi; unpack2(dlo, dhi, d2);
                if (__builtin_expect(fminf(dlo, dhi) < b_s2, 0)) {
                    float cl = (dlo < 0.0f) ? 1e-7f : dlo;
                    float ch = (dhi < 0.0f) ? 1e-7f : dhi;
                    INSERT3(cl, j,     b_s0, b_s1, b_s2, b_i0, b_i1, b_i2);
                    INSERT3(ch, j + 1, b_s0, b_s1, b_s2, b_i0, b_i1, b_i2);
                }
            }
        }
    }

    {
        size_t o = (((size_t)b * NSEG_ + seg) * M_ + m0) * 3;
        pval[o + 0] = a_s0; pval[o + 1] = a_s1; pval[o + 2] = a_s2;
        pidx[o + 0] = a_i0; pidx[o + 1] = a_i1; pidx[o + 2] = a_i2;
    }
    {
        size_t o = (((size_t)b * NSEG_ + seg) * M_ + m1) * 3;
        pval[o + 0] = b_s0; pval[o + 1] = b_s1; pval[o + 2] = b_s2;
        pidx[o + 0] = b_i0; pidx[o + 1] = b_i1; pidx[o + 2] = b_i2;
    }
}

// ---------------- merge partial top-3s + compute weights ----------------
__global__ __launch_bounds__(256) void merge_kernel(
    const float* __restrict__ pval, const int* __restrict__ pidx,
    float* __restrict__ wout, int* __restrict__ iout)
{
    const int m = blockIdx.x * 256 + threadIdx.x;
    const int b = blockIdx.y;

    float v[NSEG_ * 3];
    int   ix[NSEG_ * 3];
#pragma unroll
    for (int s = 0; s < NSEG_; s++) {
        size_t o = (((size_t)b * NSEG_ + s) * M_ + m) * 3;
#pragma unroll
        for (int k = 0; k < 3; k++) {
            v[s * 3 + k]  = pval[o + k];
            ix[s * 3 + k] = pidx[o + k];
        }
    }

    float rs[3]; int ri[3];
#pragma unroll
    for (int k = 0; k < 3; k++) {
        int best = 0;
#pragma unroll
        for (int t = 1; t < NSEG_ * 3; t++) {
            bool better = (v[t] < v[best]) ||
                          (v[t] == v[best] && ix[t] < ix[best]);
            if (better) best = t;
        }
        rs[k] = v[best]; ri[k] = ix[best];
        v[best] = FLT_MAX; ix[best] = 0x7FFFFFFF;
    }

    float w0 = __fdiv_rn(1.0f, rs[0]);
    float w1 = __fdiv_rn(1.0f, rs[1]);
    float w2 = __fdiv_rn(1.0f, rs[2]);
    float wsum = __fadd_rn(__fadd_rn(w0, w1), w2);
    size_t o = ((size_t)b * M_ + m) * 3;
    wout[o + 0] = __fdiv_rn(w0, wsum);
    wout[o + 1] = __fdiv_rn(w1, wsum);
    wout[o + 2] = __fdiv_rn(w2, wsum);
    iout[o + 0] = ri[0]; iout[o + 1] = ri[1]; iout[o + 2] = ri[2];
}

// ---------------- gather + weighted interpolation ----------------
__global__ __launch_bounds__(128) void interp_kernel(
    const float* __restrict__ featT, const float* __restrict__ wv,
    const int* __restrict__ iv, float* __restrict__ out)
{
    __shared__ float sacc[64][COUT_ + 1];
    __shared__ float sw[64 * 3];
    __shared__ int   si[64 * 3];
    const int tid = threadIdx.x;
    const int b   = blockIdx.y;
    const int m0  = blockIdx.x * 64;
    const size_t base = ((size_t)b * M_ + m0) * 3;

    for (int l = tid; l < 192; l += 128) {
        sw[l] = wv[base + l];
        si[l] = iv[base + l];
    }
    __syncthreads();

    const float* fb = featT + (size_t)b * NIN_ * COUT_;
    const int c = tid;
#pragma unroll 2
    for (int qq = 0; qq < 64; qq++) {
        float w0 = sw[qq * 3], w1 = sw[qq * 3 + 1], w2 = sw[qq * 3 + 2];
        const float* f0 = fb + (size_t)si[qq * 3]     * COUT_;
        const float* f1 = fb + (size_t)si[qq * 3 + 1] * COUT_;
        const float* f2 = fb + (size_t)si[qq * 3 + 2] * COUT_;
        sacc[qq][c] = __fmaf_rn(w2, f2[c],
                      __fmaf_rn(w1, f1[c], __fmul_rn(w0, f0[c])));
    }
    __syncthreads();

#pragma unroll
    for (int cc = 0; cc < COUT_; cc += 2) {
        int ci = cc + (tid >> 6);
        int mi = tid & 63;
        out[((size_t)b * COUT_ + ci) * M_ + m0 + mi] = sacc[mi][ci];
    }
}

// ---------------- launch ----------------
extern "C" void kernel_launch(void* const* d_in, const int* in_sizes, int n_in,
                              void* d_out, int out_size)
{
    (void)in_sizes; (void)n_in; (void)out_size;
    const float* rgb    = (const float*)d_in[0];
    const float* xyzin  = (const float*)d_in[1];
    const float* xyzout = (const float*)d_in[2];
    const float* w1 = (const float*)d_in[3];
    const float* b1 = (const float*)d_in[4];
    const float* g1 = (const float*)d_in[5];
    const float* be1 = (const float*)d_in[6];
    const float* rm1 = (const float*)d_in[7];
    const float* rv1 = (const float*)d_in[8];
    const float* w2 = (const float*)d_in[9];
    const float* b2 = (const float*)d_in[10];
    const float* g2 = (const float*)d_in[11];
    const float* be2 = (const float*)d_in[12];
    const float* rm2 = (const float*)d_in[13];
    const float* rv2 = (const float*)d_in[14];
    const float* w3 = (const float*)d_in[15];
    const float* b3 = (const float*)d_in[16];
    const float* g3 = (const float*)d_in[17];
    const float* be3 = (const float*)d_in[18];
    const float* rm3 = (const float*)d_in[19];
    const float* rv3 = (const float*)d_in[20];
    float* out = (float*)d_out;

    float *bufA, *bufB, *featT, *wvp, *pvp;
    int *ivp, *pip;
    cudaGetSymbolAddress((void**)&bufA,  g_bufA);
    cudaGetSymbolAddress((void**)&bufB,  g_bufB);
    cudaGetSymbolAddress((void**)&featT, g_featT);
    cudaGetSymbolAddress((void**)&wvp,   g_wv);
    cudaGetSymbolAddress((void**)&ivp,   g_iv);
    cudaGetSymbolAddress((void**)&pvp,   g_pval);
    cudaGetSymbolAddress((void**)&pip,   g_pidx);

    dim3 gemm_grid(NIN_ / 64, B_);
    mlp_kernel<<<gemm_grid, 256>>>(rgb,  w1, b1, g1, be1, rm1, rv1, bufA,  CIN_,  0);
    mlp_kernel<<<gemm_grid, 256>>>(bufA, w2, b2, g2, be2, rm2, rv2, bufB,  COUT_, 0);
    mlp_kernel<<<gemm_grid, 256>>>(bufB, w3, b3, g3, be3, rm3, rv3, featT, COUT_, 1);

    dim3 scan_grid(M_ / 512, NSEG_, B_);
    scan_kernel<<<scan_grid, 256>>>(xyzin, xyzout, pvp, pip);

    dim3 merge_grid(M_ / 256, B_);
    merge_kernel<<<merge_grid, 256>>>(pvp, pip, wvp, ivp);

    dim3 interp_grid(M_ / 64, B_);
    interp_kernel<<<interp_grid, 128>>>(featT, wvp, ivp, out);
}